// round 11
// baseline (speedup 1.0000x reference)
#include <cuda_runtime.h>

// RadarSparseProcessor: out[v,o] = (sum_p sum_c x[v,p,c] * W[o,c]) / max(n_v, 1)
// V = 1048576, P = 4, C_IN = 4, C_OUT = 32. vnp is int32.
//
// R11: R10 structure, but 64 voxels (2 tiles) per warp with all 8 input
// LDG.128.CS + 2 vnp loads front-batched (MLP=10 vs 5). Tests the
// latency/MLP hypothesis: occ held at ~50%, in-flight bytes per SM doubled.

#define THREADS 256
#define WARPS_PER_BLOCK (THREADS / 32)

__global__ __launch_bounds__(THREADS, 4)
void radar_sparse_kernel(const float4* __restrict__ in4,  // [V*4] float4 (= [V,4,4])
                         const float4* __restrict__ W4,   // [32] float4 (= [32,4])
                         const int*    __restrict__ vnp,  // [V] int32
                         float4* __restrict__ out4,       // [V*8] float4 (= [V,32])
                         int V)
{
    __shared__ float4 sS[WARPS_PER_BLOCK][32];    // per-warp s-vector park

    const unsigned FULL = 0xFFFFFFFFu;
    const int lane  = threadIdx.x & 31;
    const int wwarp = threadIdx.x >> 5;
    const int gwarp = (blockIdx.x * blockDim.x + threadIdx.x) >> 5;
    const int vbase = gwarp * 64;                 // first voxel of this warp (64/warp)
    if (vbase >= V) return;

    // Weight rows for this lane's channel quad q = lane&7 (channels 4q..4q+3).
    const int q = lane & 7;
    const float4 w0 = W4[q * 4 + 0];
    const float4 w1 = W4[q * 4 + 1];
    const float4 w2 = W4[q * 4 + 2];
    const float4 w3 = W4[q * 4 + 3];

    if (vbase + 64 <= V) {
        // ---------- fast path: 2 full tiles of 32 voxels ----------
        // Front-batched streaming loads: 8x LDG.128.CS (4096 B/warp) + 2 vnp.
        int n0 = __ldcs(vnp + vbase + lane);
        int n1 = __ldcs(vnp + vbase + 32 + lane);
        const float4* inBase = in4 + (size_t)vbase * 4;
        float4 d[8];
        #pragma unroll
        for (int k = 0; k < 8; k++) d[k] = __ldcs(inBase + k * 32 + lane);

        float inv0 = 1.0f / (float)(n0 > 1 ? n0 : 1);
        float inv1 = 1.0f / (float)(n1 > 1 ? n1 : 1);

        #pragma unroll
        for (int t = 0; t < 2; t++) {
            const float invl = t ? inv1 : inv0;
            float4* outBase = out4 + (size_t)(vbase + 32 * t) * 8;

            #pragma unroll
            for (int k = 0; k < 4; k++) {
                // Butterfly sum over the point dimension (4-lane groups).
                float4 s = d[4 * t + k];
                s.x += __shfl_xor_sync(FULL, s.x, 1);
                s.y += __shfl_xor_sync(FULL, s.y, 1);
                s.z += __shfl_xor_sync(FULL, s.z, 1);
                s.w += __shfl_xor_sync(FULL, s.w, 1);
                s.x += __shfl_xor_sync(FULL, s.x, 2);
                s.y += __shfl_xor_sync(FULL, s.y, 2);
                s.z += __shfl_xor_sync(FULL, s.z, 2);
                s.w += __shfl_xor_sync(FULL, s.w, 2);
                // Fold in 1/max(n,1) of voxel (32t + 8k + (l>>2)).
                float ik = __shfl_sync(FULL, invl, 8 * k + (lane >> 2));
                s.x *= ik; s.y *= ik; s.z *= ik; s.w *= ik;
                // All 4 lanes of group j=(l>>2) hold s of voxel 32t+8k+j.

                // Park s in smem: one lane per group writes -> 8 consecutive
                // float4s (128 B contiguous, conflict-free).
                if ((lane & 3) == 0) sS[wwarp][8 * k + (lane >> 2)] = s;
                __syncwarp();

                // Store iterations i = 2k, 2k+1; iter i covers voxels 4i..4i+3
                // of this tile. Lane l writes voxel 4i+(l>>3), channel quad q.
                #pragma unroll
                for (int h = 0; h < 2; h++) {
                    const int i = 2 * k + h;
                    float4 sv = sS[wwarp][4 * i + (lane >> 3)];  // 8-way bcast
                    float4 o;
                    o.x = fmaf(w0.x, sv.x, fmaf(w0.y, sv.y, fmaf(w0.z, sv.z, w0.w * sv.w)));
                    o.y = fmaf(w1.x, sv.x, fmaf(w1.y, sv.y, fmaf(w1.z, sv.z, w1.w * sv.w)));
                    o.z = fmaf(w2.x, sv.x, fmaf(w2.y, sv.y, fmaf(w2.z, sv.z, w2.w * sv.w)));
                    o.w = fmaf(w3.x, sv.x, fmaf(w3.y, sv.y, fmaf(w3.z, sv.z, w3.w * sv.w)));
                    __stcs(outBase + i * 32 + lane, o);   // contiguous 512 B/warp
                }
                __syncwarp();
            }
        }
    } else {
        // ---------- tail path: per-lane scalar (absent for V = 1M) ----------
        for (int v = vbase + lane; v < V; v += 32) {
            const float4* vrow = in4 + (size_t)v * 4;
            float4 p0 = vrow[0], p1 = vrow[1], p2 = vrow[2], p3 = vrow[3];
            int n = vnp[v];
            float inv = 1.0f / (float)(n > 1 ? n : 1);
            float sx = ((p0.x + p1.x) + (p2.x + p3.x)) * inv;
            float sy = ((p0.y + p1.y) + (p2.y + p3.y)) * inv;
            float sz = ((p0.z + p1.z) + (p2.z + p3.z)) * inv;
            float sw = ((p0.w + p1.w) + (p2.w + p3.w)) * inv;
            float4* orow = out4 + (size_t)v * 8;
            #pragma unroll
            for (int kk = 0; kk < 8; kk++) {
                float4 a = W4[kk * 4 + 0], b = W4[kk * 4 + 1];
                float4 c = W4[kk * 4 + 2], e = W4[kk * 4 + 3];
                float4 o;
                o.x = fmaf(a.x, sx, fmaf(a.y, sy, fmaf(a.z, sz, a.w * sw)));
                o.y = fmaf(b.x, sx, fmaf(b.y, sy, fmaf(b.z, sz, b.w * sw)));
                o.z = fmaf(c.x, sx, fmaf(c.y, sy, fmaf(c.z, sz, c.w * sw)));
                o.w = fmaf(e.x, sx, fmaf(e.y, sy, fmaf(e.z, sz, e.w * sw)));
                orow[kk] = o;
            }
        }
    }
}

extern "C" void kernel_launch(void* const* d_in, const int* in_sizes, int n_in,
                              void* d_out, int out_size)
{
    const float4* in4 = (const float4*)d_in[0];   // voxel_features [V,4,4] f32
    const float4* W4  = (const float4*)d_in[1];   // W [32,4] f32
    const int*    vnp = (const int*)d_in[2];      // voxel_num_points [V] i32
    float4*       out = (float4*)d_out;           // [V,32] f32

    int V = in_sizes[2];
    int warps = (V + 63) / 64;                    // 64 voxels per warp
    int blocks = (warps * 32 + THREADS - 1) / THREADS;
    radar_sparse_kernel<<<blocks, THREADS>>>(in4, W4, vnp, out, V);
}

// round 12
// speedup vs baseline: 1.0063x; 1.0063x over previous
#include <cuda_runtime.h>

// RadarSparseProcessor: out[v,o] = (sum_p sum_c x[v,p,c] * W[o,c]) / max(n_v, 1)
// V = 1048576, P = 4, C_IN = 4, C_OUT = 32. vnp is int32.
//
// R12: R10 structure with ONE change: stores are plain write-back (no
// __stcs). The 134 MB output nearly fits in the 126 MB L2; under graph
// replay the same lines are overwritten in place, so normal-evict dirty
// lines never reach DRAM. __ldcs keeps the single-use read stream
// evict-first so it doesn't displace resident output.

#define THREADS 256
#define WARPS_PER_BLOCK (THREADS / 32)

__global__ __launch_bounds__(THREADS, 5)
void radar_sparse_kernel(const float4* __restrict__ in4,  // [V*4] float4 (= [V,4,4])
                         const float4* __restrict__ W4,   // [32] float4 (= [32,4])
                         const int*    __restrict__ vnp,  // [V] int32
                         float4* __restrict__ out4,       // [V*8] float4 (= [V,32])
                         int V)
{
    __shared__ float4 sS[WARPS_PER_BLOCK][32];    // per-warp s-vector park

    const unsigned FULL = 0xFFFFFFFFu;
    const int lane  = threadIdx.x & 31;
    const int wwarp = threadIdx.x >> 5;
    const int gwarp = (blockIdx.x * blockDim.x + threadIdx.x) >> 5;
    const int vbase = gwarp * 32;                 // first voxel of this warp
    if (vbase >= V) return;

    // Weight rows for this lane's channel quad q = lane&7 (channels 4q..4q+3).
    const int q = lane & 7;
    const float4 w0 = W4[q * 4 + 0];
    const float4 w1 = W4[q * 4 + 1];
    const float4 w2 = W4[q * 4 + 2];
    const float4 w3 = W4[q * 4 + 3];

    if (vbase + 32 <= V) {
        // ---------- fast path: full warp of 32 voxels ----------
        int n = __ldcs(vnp + vbase + lane);       // coalesced 128 B, streaming
        float invl = 1.0f / (float)(n > 1 ? n : 1);

        // Front-batched streaming loads: 4x LDG.128.CS, contiguous 2048 B/warp.
        // Iter k, lane l holds point (l&3) of voxel 8k + (l>>2).
        const float4* inBase = in4 + (size_t)vbase * 4;
        float4 d[4];
        #pragma unroll
        for (int k = 0; k < 4; k++) d[k] = __ldcs(inBase + k * 32 + lane);

        float4* outBase = out4 + (size_t)vbase * 8;

        #pragma unroll
        for (int k = 0; k < 4; k++) {
            // Butterfly sum over the point dimension (4-lane groups).
            float4 s = d[k];
            s.x += __shfl_xor_sync(FULL, s.x, 1);
            s.y += __shfl_xor_sync(FULL, s.y, 1);
            s.z += __shfl_xor_sync(FULL, s.z, 1);
            s.w += __shfl_xor_sync(FULL, s.w, 1);
            s.x += __shfl_xor_sync(FULL, s.x, 2);
            s.y += __shfl_xor_sync(FULL, s.y, 2);
            s.z += __shfl_xor_sync(FULL, s.z, 2);
            s.w += __shfl_xor_sync(FULL, s.w, 2);
            // Fold in 1/max(n,1) of voxel 8k + (l>>2).
            float ik = __shfl_sync(FULL, invl, 8 * k + (lane >> 2));
            s.x *= ik; s.y *= ik; s.z *= ik; s.w *= ik;
            // All 4 lanes of group j=(l>>2) hold s of voxel 8k+j.

            // Park s in smem: one lane per group writes -> 8 consecutive
            // float4s (128 B contiguous, conflict-free, 1 wavefront).
            if ((lane & 3) == 0) sS[wwarp][8 * k + (lane >> 2)] = s;
            __syncwarp();

            // Store iterations i = 2k, 2k+1; iter i covers voxels 4i..4i+3.
            // Lane l writes voxel 4i+(l>>3), channel quad q.
            #pragma unroll
            for (int h = 0; h < 2; h++) {
                const int i = 2 * k + h;
                float4 sv = sS[wwarp][4 * i + (lane >> 3)];  // 8-way bcast LDS.128
                float4 o;
                o.x = fmaf(w0.x, sv.x, fmaf(w0.y, sv.y, fmaf(w0.z, sv.z, w0.w * sv.w)));
                o.y = fmaf(w1.x, sv.x, fmaf(w1.y, sv.y, fmaf(w1.z, sv.z, w1.w * sv.w)));
                o.z = fmaf(w2.x, sv.x, fmaf(w2.y, sv.y, fmaf(w2.z, sv.z, w2.w * sv.w)));
                o.w = fmaf(w3.x, sv.x, fmaf(w3.y, sv.y, fmaf(w3.z, sv.z, w3.w * sv.w)));
                outBase[i * 32 + lane] = o;   // plain write-back store -> L2-resident
            }
            __syncwarp();
        }
    } else {
        // ---------- tail path: per-lane scalar (absent for V = 1M) ----------
        int v = vbase + lane;
        if (v < V) {
            const float4* vrow = in4 + (size_t)v * 4;
            float4 p0 = vrow[0], p1 = vrow[1], p2 = vrow[2], p3 = vrow[3];
            int n = vnp[v];
            float inv = 1.0f / (float)(n > 1 ? n : 1);
            float sx = ((p0.x + p1.x) + (p2.x + p3.x)) * inv;
            float sy = ((p0.y + p1.y) + (p2.y + p3.y)) * inv;
            float sz = ((p0.z + p1.z) + (p2.z + p3.z)) * inv;
            float sw = ((p0.w + p1.w) + (p2.w + p3.w)) * inv;
            float4* orow = out4 + (size_t)v * 8;
            #pragma unroll
            for (int kk = 0; kk < 8; kk++) {
                float4 a = W4[kk * 4 + 0], b = W4[kk * 4 + 1];
                float4 c = W4[kk * 4 + 2], e = W4[kk * 4 + 3];
                float4 o;
                o.x = fmaf(a.x, sx, fmaf(a.y, sy, fmaf(a.z, sz, a.w * sw)));
                o.y = fmaf(b.x, sx, fmaf(b.y, sy, fmaf(b.z, sz, b.w * sw)));
                o.z = fmaf(c.x, sx, fmaf(c.y, sy, fmaf(c.z, sz, c.w * sw)));
                o.w = fmaf(e.x, sx, fmaf(e.y, sy, fmaf(e.z, sz, e.w * sw)));
                orow[kk] = o;
            }
        }
    }
}

extern "C" void kernel_launch(void* const* d_in, const int* in_sizes, int n_in,
                              void* d_out, int out_size)
{
    const float4* in4 = (const float4*)d_in[0];   // voxel_features [V,4,4] f32
    const float4* W4  = (const float4*)d_in[1];   // W [32,4] f32
    const int*    vnp = (const int*)d_in[2];      // voxel_num_points [V] i32
    float4*       out = (float4*)d_out;           // [V,32] f32

    int V = in_sizes[2];
    int warps = (V + 31) / 32;
    int blocks = (warps * 32 + THREADS - 1) / THREADS;
    radar_sparse_kernel<<<blocks, THREADS>>>(in4, W4, vnp, out, V);
}